// round 3
// baseline (speedup 1.0000x reference)
#include <cuda_runtime.h>
#include <math.h>

typedef unsigned long long u64;

#define EPSF 1e-6f
#define Bn 16
#define Cn 512
#define Nn 4096
#define Kn 64
#define NUM_STAGES 3
#define NCHUNK 8
#define PSZ (Bn * Cn * Kn)

// Scratch (no allocations allowed -> device globals)
__device__ float g_b[PSZ];                    // current bases           (2 MB)
__device__ float g_bnew[PSZ];                 // summed partials         (2 MB)
__device__ float g_att[(size_t)Bn * Nn * Kn]; // softmax attention      (16 MB)
__device__ float g_part[NCHUNK][PSZ];         // per-chunk partials     (16 MB)
__device__ float g_colsum[Bn * Kn];           // sum over N per (b,k)

// ---------------------------------------------------------------------------
// f32x2 helpers (Blackwell packed fp32 pipe)
__device__ __forceinline__ u64 dup2(float x) {
    u64 r;
    asm("mov.b64 %0, {%1, %1};" : "=l"(r) : "f"(x));
    return r;
}
__device__ __forceinline__ void fma2(u64& d, u64 a, u64 b) {
    asm("fma.rn.f32x2 %0, %1, %2, %0;" : "+l"(d) : "l"(a), "l"(b));
}
__device__ __forceinline__ float2 unpk(u64 v) {
    float2 r;
    asm("mov.b64 {%0, %1}, %2;" : "=f"(r.x), "=f"(r.y) : "l"(v));
    return r;
}

// ---------------------------------------------------------------------------
// Normalize bases (l2 over C) and broadcast to all batches.
__global__ void k_init(const float* __restrict__ bases) {
    int k = blockIdx.x;
    int tid = threadIdx.x;
    float s = 0.f;
    for (int c = tid; c < Cn; c += 128) {
        float v = bases[c * Kn + k];
        s += v * v;
    }
    __shared__ float sh[128];
    sh[tid] = s;
    __syncthreads();
    for (int o = 64; o > 0; o >>= 1) {
        if (tid < o) sh[tid] += sh[tid + o];
        __syncthreads();
    }
    float inv = 1.f / (EPSF + sqrtf(sh[0]));
    for (int c = tid; c < Cn; c += 128) {
        float v = bases[c * Kn + k] * inv;
        for (int b = 0; b < Bn; b++)
            g_b[(b * Cn + c) * Kn + k] = v;
    }
}

// ---------------------------------------------------------------------------
__global__ void k_zero_cs() {
    int i = threadIdx.x;
    if (i < Bn * Kn) g_colsum[i] = 0.f;
}

// ---------------------------------------------------------------------------
// attention[b,n,k] = softmax_k( sum_c f[b,c,n] * g_b[b,c,k] ), plus colsum.
// grid (Nn/256, Bn), block 256. Tile 256n x 64k, micro 8n x 8k, f32x2 packed
// along n-pairs; b operand pre-duplicated in shared as u64.
__global__ __launch_bounds__(256, 2) void k_att(const float* __restrict__ f) {
    int b = blockIdx.y;
    int n0 = blockIdx.x * 256;
    int tid = threadIdx.x;
    int kx = tid & 7;    // k group (8 k each)
    int nx = tid >> 3;   // n group (8 n each), 0..31

    __shared__ __align__(16) float sf[8 * 256];   // [cc][n]
    __shared__ __align__(16) u64 sbd[8 * 64];     // [cc][k] dup-packed
    __shared__ float colsh[Kn];

    u64 acc[4][8];
#pragma unroll
    for (int p = 0; p < 4; p++)
#pragma unroll
        for (int j = 0; j < 8; j++) acc[p][j] = 0ULL;

    const float* fb = f + (size_t)b * Cn * Nn;
    const float* bb = g_b + (size_t)(b * Cn) * Kn;

    for (int c0 = 0; c0 < Cn; c0 += 8) {
#pragma unroll
        for (int t = 0; t < 2; t++) {
            int i = tid + t * 256;         // 0..511
            int cc = i >> 6, n4 = i & 63;
            *(float4*)(sf + cc * 256 + n4 * 4) =
                *(const float4*)(fb + (size_t)(c0 + cc) * Nn + n0 + n4 * 4);
        }
        if (tid < 128) {
            int cc = tid >> 4, k4 = tid & 15;
            float4 v = *(const float4*)(bb + (c0 + cc) * Kn + k4 * 4);
            u64* d = sbd + cc * 64 + k4 * 4;
            d[0] = dup2(v.x); d[1] = dup2(v.y); d[2] = dup2(v.z); d[3] = dup2(v.w);
        }
        __syncthreads();
#pragma unroll
        for (int cc = 0; cc < 8; cc++) {
            const u64* ap = (const u64*)(sf + cc * 256 + nx * 8);
            u64 a0 = ap[0], a1 = ap[1], a2 = ap[2], a3 = ap[3];
            const u64* bp = sbd + cc * 64 + kx * 8;
#pragma unroll
            for (int j = 0; j < 8; j++) {
                u64 bd = bp[j];
                fma2(acc[0][j], a0, bd);
                fma2(acc[1][j], a1, bd);
                fma2(acc[2][j], a2, bd);
                fma2(acc[3][j], a3, bd);
            }
        }
        __syncthreads();
    }

    // Softmax over k (8-lane groups sharing nx; xor 1,2,4 stays in group)
    float cp[8];
#pragma unroll
    for (int j = 0; j < 8; j++) cp[j] = 0.f;
    float* attb = g_att + ((size_t)b * Nn + n0) * Kn;
#pragma unroll
    for (int np = 0; np < 4; np++) {
        float2 e[8];
#pragma unroll
        for (int j = 0; j < 8; j++) e[j] = unpk(acc[np][j]);
#pragma unroll
        for (int h = 0; h < 2; h++) {
            float rr[8];
#pragma unroll
            for (int j = 0; j < 8; j++) rr[j] = h ? e[j].y : e[j].x;
            float m = rr[0];
#pragma unroll
            for (int j = 1; j < 8; j++) m = fmaxf(m, rr[j]);
#pragma unroll
            for (int s = 1; s < 8; s <<= 1) m = fmaxf(m, __shfl_xor_sync(0xffffffffu, m, s));
            float sum = 0.f;
#pragma unroll
            for (int j = 0; j < 8; j++) { rr[j] = __expf(rr[j] - m); sum += rr[j]; }
#pragma unroll
            for (int s = 1; s < 8; s <<= 1) sum += __shfl_xor_sync(0xffffffffu, sum, s);
            float inv = 1.f / sum;
#pragma unroll
            for (int j = 0; j < 8; j++) { rr[j] *= inv; cp[j] += rr[j]; }
            int n = nx * 8 + np * 2 + h;
            float4* p = (float4*)(attb + (size_t)n * Kn + kx * 8);
            p[0] = make_float4(rr[0], rr[1], rr[2], rr[3]);
            p[1] = make_float4(rr[4], rr[5], rr[6], rr[7]);
        }
    }

    __syncthreads();
    if (tid < Kn) colsh[tid] = 0.f;
    __syncthreads();
#pragma unroll
    for (int j = 0; j < 8; j++) atomicAdd(&colsh[kx * 8 + j], cp[j]);
    __syncthreads();
    if (tid < Kn) atomicAdd(&g_colsum[b * Kn + tid], colsh[tid]);
}

// ---------------------------------------------------------------------------
// part[chunk][b,c,k] = sum_{n in chunk} f[b,c,n] * att[b,n,k]
// grid (NCHUNK, Cn/256, Bn), block 256. Tile 256c x 64k, micro 8c x 8k,
// f32x2 packed along c-pairs (f transposed in shared, stride 258).
__global__ __launch_bounds__(256, 2) void k_bnew(const float* __restrict__ f) {
    int b = blockIdx.z;
    int c0 = blockIdx.y * 256;
    int chunk = blockIdx.x;
    int tid = threadIdx.x;
    int kx = tid & 7;
    int cx = tid >> 3;   // 0..31

    __shared__ __align__(16) float sft[16 * 258];  // [nn][c] transposed, pad 258
    __shared__ __align__(16) u64 sad[16 * 64];     // [nn][k] dup-packed

    u64 acc[4][8];
#pragma unroll
    for (int p = 0; p < 4; p++)
#pragma unroll
        for (int j = 0; j < 8; j++) acc[p][j] = 0ULL;

    const float* fb = f + (size_t)b * Cn * Nn + (size_t)c0 * Nn;
    const float* ab = g_att + (size_t)b * Nn * Kn;

    for (int nb = chunk * (Nn / NCHUNK); nb < (chunk + 1) * (Nn / NCHUNK); nb += 16) {
#pragma unroll
        for (int t = 0; t < 4; t++) {
            int i = tid + t * 256;         // 0..1023
            int c = i >> 2, seg = i & 3;
            float4 v = *(const float4*)(fb + (size_t)c * Nn + nb + seg * 4);
            sft[(seg * 4 + 0) * 258 + c] = v.x;
            sft[(seg * 4 + 1) * 258 + c] = v.y;
            sft[(seg * 4 + 2) * 258 + c] = v.z;
            sft[(seg * 4 + 3) * 258 + c] = v.w;
        }
        {
            int nn = tid >> 4, k4 = tid & 15;
            float4 v = *(const float4*)(ab + (size_t)(nb + nn) * Kn + k4 * 4);
            u64* d = sad + nn * 64 + k4 * 4;
            d[0] = dup2(v.x); d[1] = dup2(v.y); d[2] = dup2(v.z); d[3] = dup2(v.w);
        }
        __syncthreads();
#pragma unroll
        for (int nn = 0; nn < 16; nn++) {
            u64 a0 = *(const u64*)(sft + nn * 258 + cx * 8 + 0);
            u64 a1 = *(const u64*)(sft + nn * 258 + cx * 8 + 2);
            u64 a2 = *(const u64*)(sft + nn * 258 + cx * 8 + 4);
            u64 a3 = *(const u64*)(sft + nn * 258 + cx * 8 + 6);
            const u64* bp = sad + nn * 64 + kx * 8;
#pragma unroll
            for (int j = 0; j < 8; j++) {
                u64 bd = bp[j];
                fma2(acc[0][j], a0, bd);
                fma2(acc[1][j], a1, bd);
                fma2(acc[2][j], a2, bd);
                fma2(acc[3][j], a3, bd);
            }
        }
        __syncthreads();
    }

    // write per-chunk partials (no atomics)
    float* pb = g_part[chunk] + ((size_t)(b * Cn + c0 + cx * 8)) * Kn + kx * 8;
#pragma unroll
    for (int p = 0; p < 4; p++) {
        float2 e[8];
#pragma unroll
        for (int j = 0; j < 8; j++) e[j] = unpk(acc[p][j]);
        float4* q0 = (float4*)(pb + (size_t)(2 * p) * Kn);
        q0[0] = make_float4(e[0].x, e[1].x, e[2].x, e[3].x);
        q0[1] = make_float4(e[4].x, e[5].x, e[6].x, e[7].x);
        float4* q1 = (float4*)(pb + (size_t)(2 * p + 1) * Kn);
        q1[0] = make_float4(e[0].y, e[1].y, e[2].y, e[3].y);
        q1[1] = make_float4(e[4].y, e[5].y, e[6].y, e[7].y);
    }
}

// ---------------------------------------------------------------------------
// g_bnew = sum over chunks of g_part (coalesced)
__global__ void k_sum() {
    int i = blockIdx.x * 256 + threadIdx.x;
    float s = 0.f;
#pragma unroll
    for (int ch = 0; ch < NCHUNK; ch++) s += g_part[ch][i];
    g_bnew[i] = s;
}

// ---------------------------------------------------------------------------
// Fused l1norm (via colsum) + l2norm over C:
//   b = b' / ((EPS+cs)*EPS + sqrt(sum_c b'^2))
__global__ void k_bnorm() {
    int blk = blockIdx.x;
    int b = blk >> 6;
    int k = blk & 63;
    int tid = threadIdx.x;

    const float* src = g_bnew + (b * Cn) * Kn + k;
    float v[4];
    float s = 0.f;
#pragma unroll
    for (int i = 0; i < 4; i++) {
        v[i] = src[(tid + i * 128) * Kn];
        s += v[i] * v[i];
    }
    __shared__ float sh[128];
    sh[tid] = s;
    __syncthreads();
    for (int o = 64; o > 0; o >>= 1) {
        if (tid < o) sh[tid] += sh[tid + o];
        __syncthreads();
    }
    float cs = g_colsum[b * Kn + k];
    float inv = 1.f / ((EPSF + cs) * EPSF + sqrtf(sh[0]));
    float* dst = g_b + (b * Cn) * Kn + k;
#pragma unroll
    for (int i = 0; i < 4; i++) dst[(tid + i * 128) * Kn] = v[i] * inv;
}

// ---------------------------------------------------------------------------
// recon[b,c,n] = sum_k g_b[b,c,k] * att[b,n,k]
// grid (Nn/64, Cn/64, Bn), block 128. Tile 64c x 64n, micro 8c x 4n.
// f32x2 packed along the reduction dim k: both operands naturally
// k-contiguous (no transpose, no dup); horizontal lo+hi add at the end.
__global__ __launch_bounds__(128) void k_recon(float* __restrict__ out) {
    int b = blockIdx.z;
    int c0 = blockIdx.y * 64;
    int n0 = blockIdx.x * 64;
    int tid = threadIdx.x;
    int nx = tid & 15;    // n lanes; thread owns n = nx + 16*j
    int cy = tid >> 4;    // 0..7; thread owns c = cy*8 + r

    __shared__ __align__(16) float sbm[64 * 64];   // [c][k]
    __shared__ __align__(16) float satr[64 * 68];  // [n][k] pad 68

    const float* bb = g_b + (size_t)((b * Cn) + c0) * Kn;
#pragma unroll
    for (int t = 0; t < 8; t++) {
        int i = tid + t * 128;
        int row = i >> 4, k4 = i & 15;
        *(float4*)(sbm + row * 64 + k4 * 4) = *(const float4*)(bb + row * Kn + k4 * 4);
    }
    const float* ab = g_att + ((size_t)b * Nn + n0) * Kn;
#pragma unroll
    for (int t = 0; t < 8; t++) {
        int i = tid + t * 128;
        int nn = i >> 4, k4 = i & 15;
        *(float4*)(satr + nn * 68 + k4 * 4) = *(const float4*)(ab + (size_t)nn * Kn + k4 * 4);
    }
    __syncthreads();

    u64 acc[8][4];
#pragma unroll
    for (int r = 0; r < 8; r++)
#pragma unroll
        for (int j = 0; j < 4; j++) acc[r][j] = 0ULL;

#pragma unroll
    for (int kp = 0; kp < Kn / 2; kp++) {
        u64 av[4];
#pragma unroll
        for (int j = 0; j < 4; j++)
            av[j] = *(const u64*)(satr + (nx + 16 * j) * 68 + 2 * kp);
#pragma unroll
        for (int r = 0; r < 8; r++) {
            u64 bv = *(const u64*)(sbm + (cy * 8 + r) * 64 + 2 * kp);
            fma2(acc[r][0], bv, av[0]);
            fma2(acc[r][1], bv, av[1]);
            fma2(acc[r][2], bv, av[2]);
            fma2(acc[r][3], bv, av[3]);
        }
    }

    float* ob = out + ((size_t)(b * Cn + c0 + cy * 8)) * Nn + n0 + nx;
#pragma unroll
    for (int r = 0; r < 8; r++)
#pragma unroll
        for (int j = 0; j < 4; j++) {
            float2 e = unpk(acc[r][j]);
            ob[(size_t)r * Nn + 16 * j] = e.x + e.y;
        }
}

// ---------------------------------------------------------------------------
extern "C" void kernel_launch(void* const* d_in, const int* in_sizes, int n_in,
                              void* d_out, int out_size) {
    const float* feats = (const float*)d_in[0];   // [16,512,64,64]
    const float* bases = (const float*)d_in[1];   // [1,512,64]
    float* out = (float*)d_out;
    (void)in_sizes; (void)n_in; (void)out_size;

    k_init<<<Kn, 128>>>(bases);

    for (int s = 0; s < NUM_STAGES; s++) {
        k_zero_cs<<<1, 1024>>>();
        {
            dim3 g(Nn / 256, Bn);
            k_att<<<g, 256>>>(feats);
        }
        {
            dim3 g(NCHUNK, Cn / 256, Bn);
            k_bnew<<<g, 256>>>(feats);
        }
        k_sum<<<PSZ / 256, 256>>>();
        k_bnorm<<<Bn * Kn, 128>>>();
    }
    {
        dim3 g(Nn / 64, Cn / 64, Bn);
        k_recon<<<g, 128>>>(out);
    }
}

// round 4
// speedup vs baseline: 2.1533x; 2.1533x over previous
#include <cuda_runtime.h>
#include <math.h>

typedef unsigned long long u64;

#define EPSF 1e-6f
#define Bn 16
#define Cn 512
#define Nn 4096
#define Kn 64
#define NUM_STAGES 3
#define NCHUNK 8
#define PSZ (Bn * Cn * Kn)

// Scratch (no allocations allowed -> device globals)
__device__ float g_b[PSZ];                    // current bases           (2 MB)
__device__ float g_bnew[PSZ];                 // summed partials         (2 MB)
__device__ float g_att[(size_t)Bn * Nn * Kn]; // softmax attention      (16 MB)
__device__ float g_part[NCHUNK][PSZ];         // per-chunk partials     (16 MB)
__device__ float g_colsum[Bn * Kn];           // sum over N per (b,k)

// ---------------------------------------------------------------------------
// f32x2 helpers (Blackwell packed fp32 pipe)
__device__ __forceinline__ u64 dup2(float x) {
    u64 r;
    asm("mov.b64 %0, {%1, %1};" : "=l"(r) : "f"(x));
    return r;
}
__device__ __forceinline__ void fma2(u64& d, u64 a, u64 b) {
    asm("fma.rn.f32x2 %0, %1, %2, %0;" : "+l"(d) : "l"(a), "l"(b));
}
__device__ __forceinline__ float2 unpk(u64 v) {
    float2 r;
    asm("mov.b64 {%0, %1}, %2;" : "=f"(r.x), "=f"(r.y) : "l"(v));
    return r;
}

// Dup-operand layout: 8 k-groups of 9 u64 (8 used + 1 pad) per row.
// Per-lane read offset = kx*9 u64 = kx*18 floats -> all 8 lanes hit distinct
// bank pairs (18 mod 32 generates {0,18,4,22,8,26,12,30}) -> conflict-free.
#define GSTR 9
#define DROW (8 * GSTR)   // 72 u64 per row

// ---------------------------------------------------------------------------
// Normalize bases (l2 over C) and broadcast to all batches.
__global__ void k_init(const float* __restrict__ bases) {
    int k = blockIdx.x;
    int tid = threadIdx.x;
    float s = 0.f;
    for (int c = tid; c < Cn; c += 128) {
        float v = bases[c * Kn + k];
        s += v * v;
    }
    __shared__ float sh[128];
    sh[tid] = s;
    __syncthreads();
    for (int o = 64; o > 0; o >>= 1) {
        if (tid < o) sh[tid] += sh[tid + o];
        __syncthreads();
    }
    float inv = 1.f / (EPSF + sqrtf(sh[0]));
    for (int c = tid; c < Cn; c += 128) {
        float v = bases[c * Kn + k] * inv;
        for (int b = 0; b < Bn; b++)
            g_b[(b * Cn + c) * Kn + k] = v;
    }
}

// ---------------------------------------------------------------------------
__global__ void k_zero_cs() {
    int i = threadIdx.x;
    if (i < Bn * Kn) g_colsum[i] = 0.f;
}

// ---------------------------------------------------------------------------
// attention[b,n,k] = softmax_k( sum_c f[b,c,n] * g_b[b,c,k] ), plus colsum.
// grid (Nn/256, Bn), block 256. Tile 256n x 64k, micro 8n x 8k, f32x2 packed
// along n-pairs; b operand pre-duplicated in shared (padded groups).
__global__ __launch_bounds__(256, 2) void k_att(const float* __restrict__ f) {
    int b = blockIdx.y;
    int n0 = blockIdx.x * 256;
    int tid = threadIdx.x;
    int kx = tid & 7;    // k group (8 k each)
    int nx = tid >> 3;   // n group (8 n each), 0..31

    __shared__ __align__(16) float sf[8 * 256];    // [cc][n]
    __shared__ __align__(16) u64 sbd[8 * DROW];    // [cc][kgroup*9+j] dup-packed
    __shared__ float colsh[Kn];

    u64 acc[4][8];
#pragma unroll
    for (int p = 0; p < 4; p++)
#pragma unroll
        for (int j = 0; j < 8; j++) acc[p][j] = 0ULL;

    const float* fb = f + (size_t)b * Cn * Nn;
    const float* bb = g_b + (size_t)(b * Cn) * Kn;

    for (int c0 = 0; c0 < Cn; c0 += 8) {
#pragma unroll
        for (int t = 0; t < 2; t++) {
            int i = tid + t * 256;         // 0..511
            int cc = i >> 6, n4 = i & 63;
            *(float4*)(sf + cc * 256 + n4 * 4) =
                *(const float4*)(fb + (size_t)(c0 + cc) * Nn + n0 + n4 * 4);
        }
        if (tid < 128) {
            int cc = tid >> 4, k4 = tid & 15;   // k = k4*4..k4*4+3
            float4 v = *(const float4*)(bb + (c0 + cc) * Kn + k4 * 4);
            u64* d = sbd + cc * DROW + (k4 >> 1) * GSTR + (k4 & 1) * 4;
            d[0] = dup2(v.x); d[1] = dup2(v.y); d[2] = dup2(v.z); d[3] = dup2(v.w);
        }
        __syncthreads();
#pragma unroll
        for (int cc = 0; cc < 8; cc++) {
            const u64* ap = (const u64*)(sf + cc * 256 + nx * 8);
            u64 a0 = ap[0], a1 = ap[1], a2 = ap[2], a3 = ap[3];
            const u64* bp = sbd + cc * DROW + kx * GSTR;
#pragma unroll
            for (int j = 0; j < 8; j++) {
                u64 bd = bp[j];
                fma2(acc[0][j], a0, bd);
                fma2(acc[1][j], a1, bd);
                fma2(acc[2][j], a2, bd);
                fma2(acc[3][j], a3, bd);
            }
        }
        __syncthreads();
    }

    // Softmax over k (8-lane groups sharing nx; xor 1,2,4 stays in group)
    float cp[8];
#pragma unroll
    for (int j = 0; j < 8; j++) cp[j] = 0.f;
    float* attb = g_att + ((size_t)b * Nn + n0) * Kn;
#pragma unroll
    for (int np = 0; np < 4; np++) {
        float2 e[8];
#pragma unroll
        for (int j = 0; j < 8; j++) e[j] = unpk(acc[np][j]);
#pragma unroll
        for (int h = 0; h < 2; h++) {
            float rr[8];
#pragma unroll
            for (int j = 0; j < 8; j++) rr[j] = h ? e[j].y : e[j].x;
            float m = rr[0];
#pragma unroll
            for (int j = 1; j < 8; j++) m = fmaxf(m, rr[j]);
#pragma unroll
            for (int s = 1; s < 8; s <<= 1) m = fmaxf(m, __shfl_xor_sync(0xffffffffu, m, s));
            float sum = 0.f;
#pragma unroll
            for (int j = 0; j < 8; j++) { rr[j] = __expf(rr[j] - m); sum += rr[j]; }
#pragma unroll
            for (int s = 1; s < 8; s <<= 1) sum += __shfl_xor_sync(0xffffffffu, sum, s);
            float inv = 1.f / sum;
#pragma unroll
            for (int j = 0; j < 8; j++) { rr[j] *= inv; cp[j] += rr[j]; }
            int n = nx * 8 + np * 2 + h;
            float4* p = (float4*)(attb + (size_t)n * Kn + kx * 8);
            p[0] = make_float4(rr[0], rr[1], rr[2], rr[3]);
            p[1] = make_float4(rr[4], rr[5], rr[6], rr[7]);
        }
    }

    __syncthreads();
    if (tid < Kn) colsh[tid] = 0.f;
    __syncthreads();
#pragma unroll
    for (int j = 0; j < 8; j++) atomicAdd(&colsh[kx * 8 + j], cp[j]);
    __syncthreads();
    if (tid < Kn) atomicAdd(&g_colsum[b * Kn + tid], colsh[tid]);
}

// ---------------------------------------------------------------------------
// part[chunk][b,c,k] = sum_{n in chunk} f[b,c,n] * att[b,n,k]
// grid (NCHUNK, Cn/256, Bn), block 256. Tile 256c x 64k, micro 8c x 8k,
// f32x2 packed along c-pairs (f transposed in shared, stride 258).
__global__ __launch_bounds__(256, 2) void k_bnew(const float* __restrict__ f) {
    int b = blockIdx.z;
    int c0 = blockIdx.y * 256;
    int chunk = blockIdx.x;
    int tid = threadIdx.x;
    int kx = tid & 7;
    int cx = tid >> 3;   // 0..31

    __shared__ __align__(16) float sft[16 * 258];   // [nn][c] transposed, pad 258
    __shared__ __align__(16) u64 sad[16 * DROW];    // [nn][kgroup*9+j] dup-packed

    u64 acc[4][8];
#pragma unroll
    for (int p = 0; p < 4; p++)
#pragma unroll
        for (int j = 0; j < 8; j++) acc[p][j] = 0ULL;

    const float* fb = f + (size_t)b * Cn * Nn + (size_t)c0 * Nn;
    const float* ab = g_att + (size_t)b * Nn * Kn;

    for (int nb = chunk * (Nn / NCHUNK); nb < (chunk + 1) * (Nn / NCHUNK); nb += 16) {
#pragma unroll
        for (int t = 0; t < 4; t++) {
            int i = tid + t * 256;         // 0..1023
            int c = i >> 2, seg = i & 3;
            float4 v = *(const float4*)(fb + (size_t)c * Nn + nb + seg * 4);
            sft[(seg * 4 + 0) * 258 + c] = v.x;
            sft[(seg * 4 + 1) * 258 + c] = v.y;
            sft[(seg * 4 + 2) * 258 + c] = v.z;
            sft[(seg * 4 + 3) * 258 + c] = v.w;
        }
        {
            int nn = tid >> 4, k4 = tid & 15;
            float4 v = *(const float4*)(ab + (size_t)(nb + nn) * Kn + k4 * 4);
            u64* d = sad + nn * DROW + (k4 >> 1) * GSTR + (k4 & 1) * 4;
            d[0] = dup2(v.x); d[1] = dup2(v.y); d[2] = dup2(v.z); d[3] = dup2(v.w);
        }
        __syncthreads();
#pragma unroll
        for (int nn = 0; nn < 16; nn++) {
            u64 a0 = *(const u64*)(sft + nn * 258 + cx * 8 + 0);
            u64 a1 = *(const u64*)(sft + nn * 258 + cx * 8 + 2);
            u64 a2 = *(const u64*)(sft + nn * 258 + cx * 8 + 4);
            u64 a3 = *(const u64*)(sft + nn * 258 + cx * 8 + 6);
            const u64* bp = sad + nn * DROW + kx * GSTR;
#pragma unroll
            for (int j = 0; j < 8; j++) {
                u64 bd = bp[j];
                fma2(acc[0][j], a0, bd);
                fma2(acc[1][j], a1, bd);
                fma2(acc[2][j], a2, bd);
                fma2(acc[3][j], a3, bd);
            }
        }
        __syncthreads();
    }

    // write per-chunk partials (no atomics)
    float* pb = g_part[chunk] + ((size_t)(b * Cn + c0 + cx * 8)) * Kn + kx * 8;
#pragma unroll
    for (int p = 0; p < 4; p++) {
        float2 e[8];
#pragma unroll
        for (int j = 0; j < 8; j++) e[j] = unpk(acc[p][j]);
        float4* q0 = (float4*)(pb + (size_t)(2 * p) * Kn);
        q0[0] = make_float4(e[0].x, e[1].x, e[2].x, e[3].x);
        q0[1] = make_float4(e[4].x, e[5].x, e[6].x, e[7].x);
        float4* q1 = (float4*)(pb + (size_t)(2 * p + 1) * Kn);
        q1[0] = make_float4(e[0].y, e[1].y, e[2].y, e[3].y);
        q1[1] = make_float4(e[4].y, e[5].y, e[6].y, e[7].y);
    }
}

// ---------------------------------------------------------------------------
// g_bnew = sum over chunks of g_part (coalesced)
__global__ void k_sum() {
    int i = blockIdx.x * 256 + threadIdx.x;
    float s = 0.f;
#pragma unroll
    for (int ch = 0; ch < NCHUNK; ch++) s += g_part[ch][i];
    g_bnew[i] = s;
}

// ---------------------------------------------------------------------------
// Fused l1norm (via colsum) + l2norm over C:
//   b = b' / ((EPS+cs)*EPS + sqrt(sum_c b'^2))
__global__ void k_bnorm() {
    int blk = blockIdx.x;
    int b = blk >> 6;
    int k = blk & 63;
    int tid = threadIdx.x;

    const float* src = g_bnew + (b * Cn) * Kn + k;
    float v[4];
    float s = 0.f;
#pragma unroll
    for (int i = 0; i < 4; i++) {
        v[i] = src[(tid + i * 128) * Kn];
        s += v[i] * v[i];
    }
    __shared__ float sh[128];
    sh[tid] = s;
    __syncthreads();
    for (int o = 64; o > 0; o >>= 1) {
        if (tid < o) sh[tid] += sh[tid + o];
        __syncthreads();
    }
    float cs = g_colsum[b * Kn + k];
    float inv = 1.f / ((EPSF + cs) * EPSF + sqrtf(sh[0]));
    float* dst = g_b + (b * Cn) * Kn + k;
#pragma unroll
    for (int i = 0; i < 4; i++) dst[(tid + i * 128) * Kn] = v[i] * inv;
}

// ---------------------------------------------------------------------------
// recon[b,c,n] = sum_k g_b[b,c,k] * att[b,n,k]
// grid (Nn/64, Cn/64, Bn), block 128. Tile 64c x 64n, micro 8c x 4n.
// f32x2 packed along the reduction dim k (both operands k-contiguous).
__global__ __launch_bounds__(128) void k_recon(float* __restrict__ out) {
    int b = blockIdx.z;
    int c0 = blockIdx.y * 64;
    int n0 = blockIdx.x * 64;
    int tid = threadIdx.x;
    int nx = tid & 15;    // n lanes; thread owns n = nx + 16*j
    int cy = tid >> 4;    // 0..7; thread owns c = cy*8 + r

    __shared__ __align__(16) float sbm[64 * 64];   // [c][k]
    __shared__ __align__(16) float satr[64 * 68];  // [n][k] pad 68

    const float* bb = g_b + (size_t)((b * Cn) + c0) * Kn;
#pragma unroll
    for (int t = 0; t < 8; t++) {
        int i = tid + t * 128;
        int row = i >> 4, k4 = i & 15;
        *(float4*)(sbm + row * 64 + k4 * 4) = *(const float4*)(bb + row * Kn + k4 * 4);
    }
    const float* ab = g_att + ((size_t)b * Nn + n0) * Kn;
#pragma unroll
    for (int t = 0; t < 8; t++) {
        int i = tid + t * 128;
        int nn = i >> 4, k4 = i & 15;
        *(float4*)(satr + nn * 68 + k4 * 4) = *(const float4*)(ab + (size_t)nn * Kn + k4 * 4);
    }
    __syncthreads();

    u64 acc[8][4];
#pragma unroll
    for (int r = 0; r < 8; r++)
#pragma unroll
        for (int j = 0; j < 4; j++) acc[r][j] = 0ULL;

#pragma unroll
    for (int kp = 0; kp < Kn / 2; kp++) {
        u64 av[4];
#pragma unroll
        for (int j = 0; j < 4; j++)
            av[j] = *(const u64*)(satr + (nx + 16 * j) * 68 + 2 * kp);
#pragma unroll
        for (int r = 0; r < 8; r++) {
            u64 bv = *(const u64*)(sbm + (cy * 8 + r) * 64 + 2 * kp);
            fma2(acc[r][0], bv, av[0]);
            fma2(acc[r][1], bv, av[1]);
            fma2(acc[r][2], bv, av[2]);
            fma2(acc[r][3], bv, av[3]);
        }
    }

    float* ob = out + ((size_t)(b * Cn + c0 + cy * 8)) * Nn + n0 + nx;
#pragma unroll
    for (int r = 0; r < 8; r++)
#pragma unroll
        for (int j = 0; j < 4; j++) {
            float2 e = unpk(acc[r][j]);
            ob[(size_t)r * Nn + 16 * j] = e.x + e.y;
        }
}

// ---------------------------------------------------------------------------
extern "C" void kernel_launch(void* const* d_in, const int* in_sizes, int n_in,
                              void* d_out, int out_size) {
    const float* feats = (const float*)d_in[0];   // [16,512,64,64]
    const float* bases = (const float*)d_in[1];   // [1,512,64]
    float* out = (float*)d_out;
    (void)in_sizes; (void)n_in; (void)out_size;

    k_init<<<Kn, 128>>>(bases);

    for (int s = 0; s < NUM_STAGES; s++) {
        k_zero_cs<<<1, 1024>>>();
        {
            dim3 g(Nn / 256, Bn);
            k_att<<<g, 256>>>(feats);
        }
        {
            dim3 g(NCHUNK, Cn / 256, Bn);
            k_bnew<<<g, 256>>>(feats);
        }
        k_sum<<<PSZ / 256, 256>>>();
        k_bnorm<<<Bn * Kn, 128>>>();
    }
    {
        dim3 g(Nn / 64, Cn / 64, Bn);
        k_recon<<<g, 128>>>(out);
    }
}